// round 7
// baseline (speedup 1.0000x reference)
#include <cuda_runtime.h>
#include <cuda_fp16.h>
#include <math.h>
#include <stdint.h>

// Problem constants
#define CB 4
#define CT 4096
#define CD 1024
#define CH 16
#define CK 64
#define CF 4096
#define CN (CB*CT)          // 16384 tokens

#define LN_EPS  1e-5f
#define DEN_EPS 1e-6f

// ---------------------------------------------------------------------------
// Scratch (allocation-free: __device__ globals)
// ---------------------------------------------------------------------------
__device__ __half gh_xn  [(size_t)CN*CD];
__device__ __half gh_q   [(size_t)CN*CD];
__device__ __half gh_k   [(size_t)CN*CD];
__device__ __half gh_v   [(size_t)CN*CD];
__device__ __half gh_attn[(size_t)CN*CD];
__device__ __half gh_y   [(size_t)CN*CD];
__device__ __half gh_h   [(size_t)CN*CF];
__device__ __half gh_w   [12u*1024u*1024u];   // fp16 weights (contiguous)
__device__ float  g_x2   [(size_t)CN*CD];
__device__ float  g_kv   [CB*CH*CK*CK];
__device__ float  g_ksum [CB*CH*CK];

// Offsets into gh_w (halves)
#define WT_Q 0u
#define WT_K (1u*1024u*1024u)
#define WT_V (2u*1024u*1024u)
#define WT_O (3u*1024u*1024u)
#define WT_1 (4u*1024u*1024u)
#define WT_2 (8u*1024u*1024u)

// ---------------------------------------------------------------------------
// Helpers
// ---------------------------------------------------------------------------
__device__ __forceinline__ uint32_t s2u(const void* p) {
    uint32_t a;
    asm("{ .reg .u64 t; cvta.to.shared.u64 t, %1; cvt.u32.u64 %0, t; }" : "=r"(a) : "l"(p));
    return a;
}
__device__ __forceinline__ void cpa16(uint32_t d, const void* s) {
    asm volatile("cp.async.cg.shared.global [%0], [%1], 16;" :: "r"(d), "l"(s));
}
#define CP_COMMIT() asm volatile("cp.async.commit_group;" ::: "memory")
#define CP_WAIT1()  asm volatile("cp.async.wait_group 1;" ::: "memory")

// ---------------------------------------------------------------------------
// LayerNorm: one block per row (1024 elems), 256 threads x float4 -> fp16 out
// ---------------------------------------------------------------------------
__device__ __forceinline__ float block_sum_256(float v, float* red) {
    #pragma unroll
    for (int o = 16; o > 0; o >>= 1) v += __shfl_xor_sync(0xffffffffu, v, o);
    if ((threadIdx.x & 31) == 0) red[threadIdx.x >> 5] = v;
    __syncthreads();
    if (threadIdx.x < 32) {
        float t = (threadIdx.x < 8) ? red[threadIdx.x] : 0.f;
        #pragma unroll
        for (int o = 4; o > 0; o >>= 1) t += __shfl_xor_sync(0xffffffffu, t, o);
        if (threadIdx.x == 0) red[8] = t;
    }
    __syncthreads();
    return red[8];
}

__global__ void ln_kernel(const float* __restrict__ x,
                          const float* __restrict__ w,
                          const float* __restrict__ b,
                          __half* __restrict__ y)
{
    __shared__ float red[9];
    int row = blockIdx.x;
    int tid = threadIdx.x;
    const float4* xr = reinterpret_cast<const float4*>(x + (size_t)row * CD);
    float4 v = xr[tid];

    float s = v.x + v.y + v.z + v.w;
    float mean = block_sum_256(s, red) * (1.f / CD);

    float dx = v.x - mean, dy = v.y - mean, dz = v.z - mean, dw = v.w - mean;
    float s2 = dx*dx + dy*dy + dz*dz + dw*dw;
    float var = block_sum_256(s2, red) * (1.f / CD);
    float rs = rsqrtf(var + LN_EPS);

    float4 wv = reinterpret_cast<const float4*>(w)[tid];
    float4 bv = reinterpret_cast<const float4*>(b)[tid];
    __half2 h0 = __floats2half2_rn(dx * rs * wv.x + bv.x, dy * rs * wv.y + bv.y);
    __half2 h1 = __floats2half2_rn(dz * rs * wv.z + bv.z, dw * rs * wv.w + bv.w);
    __half2* yp = reinterpret_cast<__half2*>(y + (size_t)row * CD + tid * 4);
    yp[0] = h0; yp[1] = h1;
}

// ---------------------------------------------------------------------------
// Merged weight convert float -> fp16 (all 6 weights, contiguous dst)
// ---------------------------------------------------------------------------
__global__ void wconv_all_kernel(const float* __restrict__ Wq, const float* __restrict__ Wk,
                                 const float* __restrict__ Wv, const float* __restrict__ Wo,
                                 const float* __restrict__ W1, const float* __restrict__ W2,
                                 __half* __restrict__ dst)
{
    int i = blockIdx.x * 256 + threadIdx.x;      // 0 .. 3M-1 float4
    const float* src;
    int local;
    if (i < (1 << 20)) {
        int seg = i >> 18, off = i & ((1 << 18) - 1);
        src = (seg == 0) ? Wq : (seg == 1) ? Wk : (seg == 2) ? Wv : Wo;
        local = off;
    } else if (i < (2 << 20)) {
        src = W1; local = i - (1 << 20);
    } else {
        src = W2; local = i - (2 << 20);
    }
    float4 v = reinterpret_cast<const float4*>(src)[local];
    __half2* d = reinterpret_cast<__half2*>(dst + (size_t)i * 4);
    d[0] = __floats2half2_rn(v.x, v.y);
    d[1] = __floats2half2_rn(v.z, v.w);
}

// ---------------------------------------------------------------------------
// fp16 tensor-core GEMM. 128x128x64 block tile, 128 threads = 4 warps
// (2M x 2N), warp tile 64x64 -> 32 m16n8k16 MMA per warp per 16-wide k-step,
// fed by 4 A-ldmatrix.x4 + 4 B-ldmatrix.x4.trans (MMA:LDSM = 4.0).
// 3-stage cp.async pipeline. fp32 accumulate.
// Smem rows: A padded to 144B (72 halves), B to 272B (136 halves).
// epi: 0=none->h, 1=phi(elu+1)->h, 2=gelu->h, 3=+res(f32)->f32
// ---------------------------------------------------------------------------
#define GBM 128
#define GBN 128
#define GBK 64
#define ASTRH 72
#define BSTRH 136
#define STG_A_H (GBM*ASTRH)        // 9216 halves
#define STG_B_H (GBK*BSTRH)        // 8704 halves
#define STG_H   (STG_A_H+STG_B_H)  // 17920 halves (35840 B)
#define NSTG 3
#define GEMM_SMEM (NSTG*STG_H*2)   // 107520 bytes

__device__ __forceinline__ void fill_stage_h(uint32_t sbase, int s,
    const __half* __restrict__ Ab, const __half* __restrict__ Wb,
    int M, int Kd, int k0, int tid)
{
    uint32_t sA = sbase + (uint32_t)s * STG_H * 2;
    uint32_t sB = sA + STG_A_H * 2;
    const __half* ap = Ab + k0;
    const __half* wp = Wb + (size_t)k0 * M;
    #pragma unroll
    for (int j = 0; j < 8; j++) {
        int e = tid + j * 128;          // 0..1023
        int r = e >> 3, c = e & 7;      // A: 128 rows x 8 16B-chunks
        cpa16(sA + r * 144 + c * 16, ap + (size_t)r * Kd + c * 8);
    }
    #pragma unroll
    for (int j = 0; j < 8; j++) {
        int e = tid + j * 128;
        int r = e >> 4, c = e & 15;     // B: 64 rows x 16 16B-chunks
        cpa16(sB + r * 272 + c * 16, wp + (size_t)r * M + c * 8);
    }
}

__global__ __launch_bounds__(128, 2) void gemm_h_kernel(
    const __half* __restrict__ A, const __half* __restrict__ W,
    const float* __restrict__ bias, const float* __restrict__ res,
    void* __restrict__ Cout, int M, int Kd, int epi)
{
    extern __shared__ __half smem[];
    uint32_t sbase = s2u(smem);

    int tid  = threadIdx.x;
    int warp = tid >> 5;
    int lane = tid & 31;
    int g  = lane >> 2;
    int th = lane & 3;
    int wm = (warp & 1) * 64;       // warp M offset
    int wn = (warp >> 1) * 64;      // warp N offset

    int bm = blockIdx.y * GBM;
    int bn = blockIdx.x * GBN;

    const __half* Aptr = A + (size_t)bm * Kd;
    const __half* Wptr = W + bn;

    float acc[4][8][4];
    #pragma unroll
    for (int i = 0; i < 4; i++)
        #pragma unroll
        for (int j = 0; j < 8; j++)
            #pragma unroll
            for (int c = 0; c < 4; c++) acc[i][j][c] = 0.f;

    int NB = Kd >> 6;

    fill_stage_h(sbase, 0, Aptr, Wptr, M, Kd, 0, tid);
    CP_COMMIT();
    fill_stage_h(sbase, 1, Aptr, Wptr, M, Kd, GBK, tid);
    CP_COMMIT();

    // hoisted ldmatrix lane-address components
    uint32_t aOff = (uint32_t)((wm + (lane & 15)) * 144 + ((lane >> 4) << 3) * 2);
    uint32_t bOffRow = (uint32_t)((lane & 7) * 272);
    uint32_t bOffCol = (uint32_t)((wn + ((lane >> 3) << 3)) * 2);

    int s = 0;
    for (int i = 0; i < NB; i++) {
        CP_WAIT1();
        __syncthreads();

        if (i + 2 < NB) {
            int s2 = s + 2; if (s2 >= NSTG) s2 -= NSTG;
            fill_stage_h(sbase, s2, Aptr, Wptr, M, Kd, (i + 2) * GBK, tid);
            CP_COMMIT();
        }

        uint32_t sA = sbase + (uint32_t)s * STG_H * 2;
        uint32_t sB = sA + STG_A_H * 2;
        uint32_t aBase = sA + aOff;
        uint32_t bBase = sB + bOffRow + bOffCol;

        #pragma unroll
        for (int ks = 0; ks < GBK; ks += 16) {
            unsigned af[4][4], bf[8][2];
            #pragma unroll
            for (int mt = 0; mt < 4; mt++) {
                uint32_t addr = aBase + mt * (16 * 144) + ks * 2;
                asm volatile(
                    "ldmatrix.sync.aligned.m8n8.x4.shared.b16 {%0,%1,%2,%3}, [%4];"
                    : "=r"(af[mt][0]), "=r"(af[mt][1]), "=r"(af[mt][2]), "=r"(af[mt][3])
                    : "r"(addr));
            }
            #pragma unroll
            for (int nh = 0; nh < 2; nh++) {
                #pragma unroll
                for (int kh = 0; kh < 2; kh++) {
                    uint32_t addr = bBase + (ks + kh * 8) * 272 + nh * (32 * 2);
                    unsigned r0, r1, r2, r3;
                    asm volatile(
                        "ldmatrix.sync.aligned.m8n8.x4.trans.shared.b16 {%0,%1,%2,%3}, [%4];"
                        : "=r"(r0), "=r"(r1), "=r"(r2), "=r"(r3) : "r"(addr));
                    bf[nh * 4 + 0][kh] = r0; bf[nh * 4 + 1][kh] = r1;
                    bf[nh * 4 + 2][kh] = r2; bf[nh * 4 + 3][kh] = r3;
                }
            }
            #pragma unroll
            for (int mt = 0; mt < 4; mt++)
                #pragma unroll
                for (int nt = 0; nt < 8; nt++) {
                    asm volatile(
                        "mma.sync.aligned.m16n8k16.row.col.f32.f16.f16.f32 "
                        "{%0,%1,%2,%3}, {%4,%5,%6,%7}, {%8,%9}, {%0,%1,%2,%3};"
                        : "+f"(acc[mt][nt][0]), "+f"(acc[mt][nt][1]),
                          "+f"(acc[mt][nt][2]), "+f"(acc[mt][nt][3])
                        : "r"(af[mt][0]), "r"(af[mt][1]), "r"(af[mt][2]), "r"(af[mt][3]),
                          "r"(bf[nt][0]), "r"(bf[nt][1]));
                }
        }
        if (++s >= NSTG) s -= NSTG;
    }

    // ---- Epilogue ----
    __half* Ch = (__half*)Cout;
    float*  Cf = (float*)Cout;
    #pragma unroll
    for (int mt = 0; mt < 4; mt++) {
        #pragma unroll
        for (int nt = 0; nt < 8; nt++) {
            int col = bn + wn + nt * 8 + 2 * th;
            float b0 = bias[col], b1 = bias[col + 1];
            #pragma unroll
            for (int hrow = 0; hrow < 2; hrow++) {
                int row = bm + wm + mt * 16 + g + hrow * 8;
                float v0 = acc[mt][nt][2 * hrow]     + b0;
                float v1 = acc[mt][nt][2 * hrow + 1] + b1;
                if (epi == 1) {
                    v0 = (v0 > 0.f) ? (v0 + 1.f) : expf(v0);
                    v1 = (v1 > 0.f) ? (v1 + 1.f) : expf(v1);
                } else if (epi == 2) {
                    v0 = 0.5f * v0 * (1.f + erff(v0 * 0.7071067811865475f));
                    v1 = 0.5f * v1 * (1.f + erff(v1 * 0.7071067811865475f));
                }
                if (epi == 3) {
                    const float2 r2 = *reinterpret_cast<const float2*>(
                        res + (size_t)row * M + col);
                    float2 o2 = make_float2(v0 + r2.x, v1 + r2.y);
                    *reinterpret_cast<float2*>(Cf + (size_t)row * M + col) = o2;
                } else {
                    *reinterpret_cast<__half2*>(Ch + (size_t)row * M + col) =
                        __floats2half2_rn(v0, v1);
                }
            }
        }
    }
}

// ---------------------------------------------------------------------------
// Zero a float buffer
// ---------------------------------------------------------------------------
__global__ void zero_kernel(float* p, int n) {
    int i = blockIdx.x * 256 + threadIdx.x;
    if (i < n) p[i] = 0.f;
}

// ---------------------------------------------------------------------------
// kv[bh][k][v] = sum_s keep_s * phi_k[s][k] * v[s][v]  ;  ksum[bh][k]
// ---------------------------------------------------------------------------
__global__ void kv_kernel(const __half* __restrict__ pk,
                          const __half* __restrict__ vv,
                          const unsigned char* __restrict__ mask)
{
    __shared__ float sp[8][CK];
    __shared__ float sv[8][CK];

    int bh = blockIdx.x;
    int chunk = blockIdx.y;
    int b = bh / CH, h = bh % CH;
    int t0 = chunk * (CT / 8);

    int tid = threadIdx.x;
    int r0 = (tid >> 4) << 2;
    int c0 = (tid & 15) << 2;

    float acc[4][4];
    #pragma unroll
    for (int i = 0; i < 4; i++)
        #pragma unroll
        for (int j = 0; j < 4; j++) acc[i][j] = 0.f;
    float ks = 0.f;

    for (int g = 0; g < 512; g += 8) {
        #pragma unroll
        for (int i = 0; i < 2; i++) {
            int e = tid + i * 256;
            int s = e >> 6, col = e & 63;
            int t = t0 + g + s;
            size_t rowm = (size_t)b * CT + t;
            float keep = mask[rowm] ? 0.f : 1.f;
            size_t idx = rowm * CD + (size_t)h * CK + col;
            sp[s][col] = __half2float(pk[idx]) * keep;
            sv[s][col] = __half2float(vv[idx]) * keep;
        }
        __syncthreads();
        #pragma unroll
        for (int s = 0; s < 8; s++) {
            float4 a  = *reinterpret_cast<const float4*>(&sp[s][r0]);
            float4 bb = *reinterpret_cast<const float4*>(&sv[s][c0]);
            float ar[4] = {a.x, a.y, a.z, a.w};
            float br[4] = {bb.x, bb.y, bb.z, bb.w};
            #pragma unroll
            for (int i = 0; i < 4; i++)
                #pragma unroll
                for (int j = 0; j < 4; j++)
                    acc[i][j] += ar[i] * br[j];
        }
        if (tid < CK) {
            #pragma unroll
            for (int s = 0; s < 8; s++) ks += sp[s][tid];
        }
        __syncthreads();
    }

    float* kvp = g_kv + (size_t)bh * CK * CK;
    #pragma unroll
    for (int i = 0; i < 4; i++)
        #pragma unroll
        for (int j = 0; j < 4; j++)
            atomicAdd(&kvp[(r0 + i) * CK + c0 + j], acc[i][j]);
    if (tid < CK) atomicAdd(&g_ksum[bh * CK + tid], ks);
}

// ---------------------------------------------------------------------------
// attn[t][c] = (phi_q[t] . kv[:,c]) / (phi_q[t] . ksum + eps)  (fp16 out)
// ---------------------------------------------------------------------------
__global__ void attn_kernel(const __half* __restrict__ pq,
                            __half* __restrict__ attn)
{
    __shared__ float skv[CK][CK];
    __shared__ float sks[CK];
    __shared__ float sq[8][CK];

    int bh = blockIdx.x, tb = blockIdx.y;
    int b = bh / CH, h = bh % CH;
    int tid = threadIdx.x;

    const float* kvp = g_kv + (size_t)bh * CK * CK;
    for (int i = tid; i < CK * CK; i += 256) skv[i >> 6][i & 63] = kvp[i];
    if (tid < CK) sks[tid] = g_ksum[bh * CK + tid];
    __syncthreads();

    int w = tid >> 5, l = tid & 31;
    for (int it = 0; it < 16; it++) {
        int t = tb * 128 + w * 16 + it;
        size_t rowp = ((size_t)b * CT + t) * CD + (size_t)h * CK;
        sq[w][l]      = __half2float(pq[rowp + l]);
        sq[w][l + 32] = __half2float(pq[rowp + l + 32]);
        __syncwarp();
        float n0 = 0.f, n1 = 0.f, den = DEN_EPS;
        #pragma unroll
        for (int k = 0; k < CK; k++) {
            float qv = sq[w][k];
            n0  += qv * skv[k][l];
            n1  += qv * skv[k][l + 32];
            den += qv * sks[k];
        }
        float inv = 1.f / den;
        attn[rowp + l]      = __float2half_rn(n0 * inv);
        attn[rowp + l + 32] = __float2half_rn(n1 * inv);
        __syncwarp();
    }
}

// ---------------------------------------------------------------------------
// Host launcher
// ---------------------------------------------------------------------------
extern "C" void kernel_launch(void* const* d_in, const int* in_sizes, int n_in,
                              void* d_out, int out_size)
{
    const float* x    = (const float*)d_in[0];
    const unsigned char* mask = (const unsigned char*)d_in[1];
    const float* Wq   = (const float*)d_in[2];
    const float* bq   = (const float*)d_in[3];
    const float* Wk   = (const float*)d_in[4];
    const float* bk   = (const float*)d_in[5];
    const float* Wv   = (const float*)d_in[6];
    const float* bv   = (const float*)d_in[7];
    const float* Wo   = (const float*)d_in[8];
    const float* bo   = (const float*)d_in[9];
    const float* ln1w = (const float*)d_in[10];
    const float* ln1b = (const float*)d_in[11];
    const float* ln2w = (const float*)d_in[12];
    const float* ln2b = (const float*)d_in[13];
    const float* W1   = (const float*)d_in[14];
    const float* b1   = (const float*)d_in[15];
    const float* W2   = (const float*)d_in[16];
    const float* b2   = (const float*)d_in[17];
    float* out = (float*)d_out;

    void *pxn, *pq, *pk, *pv, *pattn, *py, *ph, *pwh, *px2, *pkv, *pks;
    cudaGetSymbolAddress(&pxn, gh_xn);
    cudaGetSymbolAddress(&pq, gh_q);
    cudaGetSymbolAddress(&pk, gh_k);
    cudaGetSymbolAddress(&pv, gh_v);
    cudaGetSymbolAddress(&pattn, gh_attn);
    cudaGetSymbolAddress(&py, gh_y);
    cudaGetSymbolAddress(&ph, gh_h);
    cudaGetSymbolAddress(&pwh, gh_w);
    cudaGetSymbolAddress(&px2, g_x2);
    cudaGetSymbolAddress(&pkv, g_kv);
    cudaGetSymbolAddress(&pks, g_ksum);

    __half* xn  = (__half*)pxn;
    __half* qb  = (__half*)pq;
    __half* kb  = (__half*)pk;
    __half* vb  = (__half*)pv;
    __half* atb = (__half*)pattn;
    __half* yb  = (__half*)py;
    __half* hb  = (__half*)ph;
    __half* wh  = (__half*)pwh;
    float*  x2  = (float*)px2;
    float*  kvb = (float*)pkv;
    float*  ksb = (float*)pks;

    cudaFuncSetAttribute(gemm_h_kernel, cudaFuncAttributeMaxDynamicSharedMemorySize, GEMM_SMEM);

    // 0. Convert all weights to fp16 in one launch
    wconv_all_kernel<<<12288, 256>>>(Wq, Wk, Wv, Wo, W1, W2, wh);

    // 1. LN1 -> fp16
    ln_kernel<<<CN, 256>>>(x, ln1w, ln1b, xn);

    // 2-4. QKV projections (phi fused into Q,K), fp16 out
    dim3 gD(CD / GBN, CN / GBM);
    gemm_h_kernel<<<gD, 128, GEMM_SMEM>>>(xn, wh + WT_Q, bq, nullptr, qb, CD, CD, 1);
    gemm_h_kernel<<<gD, 128, GEMM_SMEM>>>(xn, wh + WT_K, bk, nullptr, kb, CD, CD, 1);
    gemm_h_kernel<<<gD, 128, GEMM_SMEM>>>(xn, wh + WT_V, bv, nullptr, vb, CD, CD, 0);

    // 5. zero kv/ksum accumulators
    zero_kernel<<<(CB*CH*CK*CK + 255) / 256, 256>>>(kvb, CB*CH*CK*CK);
    zero_kernel<<<(CB*CH*CK + 255) / 256, 256>>>(ksb, CB*CH*CK);

    // 6. kv + ksum reduction (masked)
    kv_kernel<<<dim3(CB*CH, 8), 256>>>(kb, vb, mask);

    // 7. numerator / denominator -> fp16
    attn_kernel<<<dim3(CB*CH, CT / 128), 256>>>(qb, atb);

    // 8. O projection + residual -> fp32 x2
    gemm_h_kernel<<<gD, 128, GEMM_SMEM>>>(atb, wh + WT_O, bo, x, x2, CD, CD, 3);

    // 9. LN2 -> fp16
    ln_kernel<<<CN, 256>>>(x2, ln2w, ln2b, yb);

    // 10. FFN1 + exact GELU -> fp16
    dim3 gF(CF / GBN, CN / GBM);
    gemm_h_kernel<<<gF, 128, GEMM_SMEM>>>(yb, wh + WT_1, b1, nullptr, hb, CF, CD, 2);

    // 11. FFN2 + residual -> fp32 output
    gemm_h_kernel<<<gD, 128, GEMM_SMEM>>>(hb, wh + WT_2, b2, x2, out, CD, CF, 3);
}

// round 8
// speedup vs baseline: 1.0373x; 1.0373x over previous
#include <cuda_runtime.h>
#include <cuda_fp16.h>
#include <math.h>
#include <stdint.h>

// Problem constants
#define CB 4
#define CT 4096
#define CD 1024
#define CH 16
#define CK 64
#define CF 4096
#define CN (CB*CT)          // 16384 tokens
#define C3 3072             // fused QKV width

#define LN_EPS  1e-5f
#define DEN_EPS 1e-6f

// ---------------------------------------------------------------------------
// Scratch (allocation-free: __device__ globals)
// ---------------------------------------------------------------------------
__device__ __half gh_xn  [(size_t)CN*CD];
__device__ __half gh_qkv [(size_t)CN*C3];
__device__ __half gh_attn[(size_t)CN*CD];
__device__ __half gh_y   [(size_t)CN*CD];
__device__ __half gh_h   [(size_t)CN*CF];
__device__ __half gh_w   [12u*1024u*1024u];   // fp16 weights
__device__ float  g_x2   [(size_t)CN*CD];
__device__ float  g_kv   [CB*CH*CK*CK];
__device__ float  g_ksum [CB*CH*CK];
__device__ float  g_bqkv [C3];

// gh_w layout (halves): [0,3M) QKV packed [k][seg*1024+m], [3M,4M) O,
// [4M,8M) W1, [8M,12M) W2
#define WT_O (3u*1024u*1024u)
#define WT_1 (4u*1024u*1024u)
#define WT_2 (8u*1024u*1024u)

// ---------------------------------------------------------------------------
// Helpers
// ---------------------------------------------------------------------------
__device__ __forceinline__ uint32_t s2u(const void* p) {
    uint32_t a;
    asm("{ .reg .u64 t; cvta.to.shared.u64 t, %1; cvt.u32.u64 %0, t; }" : "=r"(a) : "l"(p));
    return a;
}
__device__ __forceinline__ void cpa16(uint32_t d, const void* s) {
    asm volatile("cp.async.cg.shared.global [%0], [%1], 16;" :: "r"(d), "l"(s));
}
#define CP_COMMIT() asm volatile("cp.async.commit_group;" ::: "memory")
#define CP_WAIT1()  asm volatile("cp.async.wait_group 1;" ::: "memory")

// ---------------------------------------------------------------------------
// LayerNorm -> fp16
// ---------------------------------------------------------------------------
__device__ __forceinline__ float block_sum_256(float v, float* red) {
    #pragma unroll
    for (int o = 16; o > 0; o >>= 1) v += __shfl_xor_sync(0xffffffffu, v, o);
    if ((threadIdx.x & 31) == 0) red[threadIdx.x >> 5] = v;
    __syncthreads();
    if (threadIdx.x < 32) {
        float t = (threadIdx.x < 8) ? red[threadIdx.x] : 0.f;
        #pragma unroll
        for (int o = 4; o > 0; o >>= 1) t += __shfl_xor_sync(0xffffffffu, t, o);
        if (threadIdx.x == 0) red[8] = t;
    }
    __syncthreads();
    return red[8];
}

__global__ void ln_kernel(const float* __restrict__ x,
                          const float* __restrict__ w,
                          const float* __restrict__ b,
                          __half* __restrict__ y)
{
    __shared__ float red[9];
    int row = blockIdx.x;
    int tid = threadIdx.x;
    const float4* xr = reinterpret_cast<const float4*>(x + (size_t)row * CD);
    float4 v = xr[tid];

    float s = v.x + v.y + v.z + v.w;
    float mean = block_sum_256(s, red) * (1.f / CD);

    float dx = v.x - mean, dy = v.y - mean, dz = v.z - mean, dw = v.w - mean;
    float s2 = dx*dx + dy*dy + dz*dz + dw*dw;
    float var = block_sum_256(s2, red) * (1.f / CD);
    float rs = rsqrtf(var + LN_EPS);

    float4 wv = reinterpret_cast<const float4*>(w)[tid];
    float4 bv = reinterpret_cast<const float4*>(b)[tid];
    __half2 h0 = __floats2half2_rn(dx * rs * wv.x + bv.x, dy * rs * wv.y + bv.y);
    __half2 h1 = __floats2half2_rn(dz * rs * wv.z + bv.z, dw * rs * wv.w + bv.w);
    __half2* yp = reinterpret_cast<__half2*>(y + (size_t)row * CD + tid * 4);
    yp[0] = h0; yp[1] = h1;
}

// ---------------------------------------------------------------------------
// Weight convert. QKV packed interleaved: dst[k*3072 + seg*1024 + m].
// O/W1/W2 contiguous as before. Also concat bias into g_bqkv.
// ---------------------------------------------------------------------------
__global__ void wconv_all_kernel(const float* __restrict__ Wq, const float* __restrict__ Wk,
                                 const float* __restrict__ Wv, const float* __restrict__ Wo,
                                 const float* __restrict__ W1, const float* __restrict__ W2,
                                 const float* __restrict__ bq, const float* __restrict__ bk,
                                 const float* __restrict__ bv,
                                 __half* __restrict__ dst)
{
    int i = blockIdx.x * 256 + threadIdx.x;      // 0 .. 3M-1 float4
    if (i < C3 && blockIdx.x < 12) {             // concat bias (first 12 blocks cover 3072)
        float v = (i < 1024) ? bq[i] : (i < 2048) ? bk[i - 1024] : bv[i - 2048];
        g_bqkv[i] = v;
    }
    if (i < (3 << 18)) {                          // QKV packed: 3 x 256K f4
        int seg = i >> 18, off = i & ((1 << 18) - 1);
        const float* src = (seg == 0) ? Wq : (seg == 1) ? Wk : Wv;
        float4 v = reinterpret_cast<const float4*>(src)[off];
        int k  = off >> 8;                        // 256 f4 per 1024-float row
        int c4 = off & 255;
        __half* d = dst + (size_t)k * C3 + seg * 1024 + c4 * 4;
        reinterpret_cast<__half2*>(d)[0] = __floats2half2_rn(v.x, v.y);
        reinterpret_cast<__half2*>(d)[1] = __floats2half2_rn(v.z, v.w);
        return;
    }
    const float* src; size_t dsto; int local;
    if (i < (1 << 20))      { src = Wo; dsto = WT_O; local = i - (3 << 18); }
    else if (i < (2 << 20)) { src = W1; dsto = WT_1; local = i - (1 << 20); }
    else                    { src = W2; dsto = WT_2; local = i - (2 << 20); }
    float4 v = reinterpret_cast<const float4*>(src)[local];
    __half* d = dst + dsto + (size_t)local * 4;
    reinterpret_cast<__half2*>(d)[0] = __floats2half2_rn(v.x, v.y);
    reinterpret_cast<__half2*>(d)[1] = __floats2half2_rn(v.z, v.w);
}

// ---------------------------------------------------------------------------
// fp16 tensor-core GEMM (R5 config + hoisted addressing).
// 128x128x64 block tile, 256 threads = 8 warps (2M x 4N), warp tile 64x32.
// 3-stage cp.async. epi: 0=none->h, 2=gelu->h, 3=+res(f32)->f32,
// 4=qkv (phi on cols<2048)->h
// ---------------------------------------------------------------------------
#define GBM 128
#define GBN 128
#define GBK 64
#define STG_A_H (GBM*72)           // 9216 halves, 144B rows
#define STG_B_H (GBK*136)          // 8704 halves, 272B rows
#define STG_H   (STG_A_H+STG_B_H)  // 17920 halves
#define NSTG 3
#define GEMM_SMEM (NSTG*STG_H*2)   // 107520 bytes

__device__ __forceinline__ void fill_stage_h(uint32_t sbase, int s,
    const __half* __restrict__ Ab, const __half* __restrict__ Wb,
    int M, int Kd, int k0, int tid)
{
    uint32_t sA = sbase + (uint32_t)s * STG_H * 2;
    uint32_t sB = sA + STG_A_H * 2;
    const __half* ap = Ab + k0;
    const __half* wp = Wb + (size_t)k0 * M;
    #pragma unroll
    for (int j = 0; j < 4; j++) {
        int e = tid + j * 256;          // 0..1023
        int r = e >> 3, c = e & 7;      // A: 128 rows x 8 chunks
        cpa16(sA + r * 144 + c * 16, ap + (size_t)r * Kd + c * 8);
    }
    #pragma unroll
    for (int j = 0; j < 4; j++) {
        int e = tid + j * 256;
        int r = e >> 4, c = e & 15;     // B: 64 rows x 16 chunks
        cpa16(sB + r * 272 + c * 16, wp + (size_t)r * M + c * 8);
    }
}

__global__ __launch_bounds__(256, 2) void gemm_h_kernel(
    const __half* __restrict__ A, const __half* __restrict__ W,
    const float* __restrict__ bias, const float* __restrict__ res,
    void* __restrict__ Cout, int M, int Kd, int epi)
{
    extern __shared__ __half smem[];
    uint32_t sbase = s2u(smem);

    int tid  = threadIdx.x;
    int warp = tid >> 5;
    int lane = tid & 31;
    int g  = lane >> 2;
    int th = lane & 3;
    int wm = (warp & 1) * 64;
    int wn = (warp >> 1) * 32;

    int bm = blockIdx.y * GBM;
    int bn = blockIdx.x * GBN;

    const __half* Aptr = A + (size_t)bm * Kd;
    const __half* Wptr = W + bn;

    float acc[4][4][4];
    #pragma unroll
    for (int i = 0; i < 4; i++)
        #pragma unroll
        for (int j = 0; j < 4; j++)
            #pragma unroll
            for (int c = 0; c < 4; c++) acc[i][j][c] = 0.f;

    int NB = Kd >> 6;

    fill_stage_h(sbase, 0, Aptr, Wptr, M, Kd, 0, tid);
    CP_COMMIT();
    fill_stage_h(sbase, 1, Aptr, Wptr, M, Kd, GBK, tid);
    CP_COMMIT();

    // hoisted per-warp ldmatrix offsets (immediates after unroll)
    uint32_t aOff = (uint32_t)((wm + (lane & 15)) * 144 + (((lane >> 4) << 3)) * 2);
    uint32_t bOff = (uint32_t)((lane & 7) * 272 + (wn + ((lane >> 3) << 3)) * 2);

    int s = 0;
    for (int i = 0; i < NB; i++) {
        CP_WAIT1();
        __syncthreads();

        if (i + 2 < NB) {
            int s2 = s + 2; if (s2 >= NSTG) s2 -= NSTG;
            fill_stage_h(sbase, s2, Aptr, Wptr, M, Kd, (i + 2) * GBK, tid);
            CP_COMMIT();
        }

        uint32_t aBase = sbase + (uint32_t)s * STG_H * 2 + aOff;
        uint32_t bBase = sbase + (uint32_t)s * STG_H * 2 + STG_A_H * 2 + bOff;

        #pragma unroll
        for (int ks = 0; ks < GBK; ks += 16) {
            unsigned af[4][4], bf[4][2];
            #pragma unroll
            for (int mt = 0; mt < 4; mt++) {
                uint32_t addr = aBase + mt * (16 * 144) + ks * 2;
                asm volatile(
                    "ldmatrix.sync.aligned.m8n8.x4.shared.b16 {%0,%1,%2,%3}, [%4];"
                    : "=r"(af[mt][0]), "=r"(af[mt][1]), "=r"(af[mt][2]), "=r"(af[mt][3])
                    : "r"(addr));
            }
            #pragma unroll
            for (int kh = 0; kh < 2; kh++) {
                uint32_t addr = bBase + (ks + kh * 8) * 272;
                unsigned r0, r1, r2, r3;
                asm volatile(
                    "ldmatrix.sync.aligned.m8n8.x4.trans.shared.b16 {%0,%1,%2,%3}, [%4];"
                    : "=r"(r0), "=r"(r1), "=r"(r2), "=r"(r3) : "r"(addr));
                bf[0][kh] = r0; bf[1][kh] = r1; bf[2][kh] = r2; bf[3][kh] = r3;
            }
            #pragma unroll
            for (int mt = 0; mt < 4; mt++)
                #pragma unroll
                for (int nt = 0; nt < 4; nt++) {
                    asm volatile(
                        "mma.sync.aligned.m16n8k16.row.col.f32.f16.f16.f32 "
                        "{%0,%1,%2,%3}, {%4,%5,%6,%7}, {%8,%9}, {%0,%1,%2,%3};"
                        : "+f"(acc[mt][nt][0]), "+f"(acc[mt][nt][1]),
                          "+f"(acc[mt][nt][2]), "+f"(acc[mt][nt][3])
                        : "r"(af[mt][0]), "r"(af[mt][1]), "r"(af[mt][2]), "r"(af[mt][3]),
                          "r"(bf[nt][0]), "r"(bf[nt][1]));
                }
        }
        if (++s >= NSTG) s -= NSTG;
    }

    // ---- Epilogue ----
    __half* Ch = (__half*)Cout;
    float*  Cf = (float*)Cout;
    #pragma unroll
    for (int mt = 0; mt < 4; mt++) {
        #pragma unroll
        for (int nt = 0; nt < 4; nt++) {
            int col = bn + wn + nt * 8 + 2 * th;
            float b0 = bias[col], b1 = bias[col + 1];
            #pragma unroll
            for (int hrow = 0; hrow < 2; hrow++) {
                int row = bm + wm + mt * 16 + g + hrow * 8;
                float v0 = acc[mt][nt][2 * hrow]     + b0;
                float v1 = acc[mt][nt][2 * hrow + 1] + b1;
                if (epi == 4) {
                    if (col < 2048) {
                        v0 = (v0 > 0.f) ? (v0 + 1.f) : expf(v0);
                        v1 = (v1 > 0.f) ? (v1 + 1.f) : expf(v1);
                    }
                } else if (epi == 2) {
                    v0 = 0.5f * v0 * (1.f + erff(v0 * 0.7071067811865475f));
                    v1 = 0.5f * v1 * (1.f + erff(v1 * 0.7071067811865475f));
                }
                if (epi == 3) {
                    const float2 r2 = *reinterpret_cast<const float2*>(
                        res + (size_t)row * M + col);
                    float2 o2 = make_float2(v0 + r2.x, v1 + r2.y);
                    *reinterpret_cast<float2*>(Cf + (size_t)row * M + col) = o2;
                } else {
                    *reinterpret_cast<__half2*>(Ch + (size_t)row * M + col) =
                        __floats2half2_rn(v0, v1);
                }
            }
        }
    }
}

// ---------------------------------------------------------------------------
// Zero a float buffer
// ---------------------------------------------------------------------------
__global__ void zero_kernel(float* p, int n) {
    int i = blockIdx.x * 256 + threadIdx.x;
    if (i < n) p[i] = 0.f;
}

// ---------------------------------------------------------------------------
// kv[bh][k][v] = sum_s keep_s * phi_k[s][k] * v[s][v]  ;  ksum[bh][k]
// reads fused qkv buffer (stride C3): K at +1024, V at +2048
// ---------------------------------------------------------------------------
__global__ void kv_kernel(const __half* __restrict__ qkv,
                          const unsigned char* __restrict__ mask)
{
    __shared__ float sp[8][CK];
    __shared__ float sv[8][CK];

    int bh = blockIdx.x;
    int chunk = blockIdx.y;
    int b = bh / CH, h = bh % CH;
    int t0 = chunk * (CT / 8);

    int tid = threadIdx.x;
    int r0 = (tid >> 4) << 2;
    int c0 = (tid & 15) << 2;

    float acc[4][4];
    #pragma unroll
    for (int i = 0; i < 4; i++)
        #pragma unroll
        for (int j = 0; j < 4; j++) acc[i][j] = 0.f;
    float ks = 0.f;

    for (int g = 0; g < 512; g += 8) {
        #pragma unroll
        for (int i = 0; i < 2; i++) {
            int e = tid + i * 256;
            int s = e >> 6, col = e & 63;
            int t = t0 + g + s;
            size_t rowm = (size_t)b * CT + t;
            float keep = mask[rowm] ? 0.f : 1.f;
            size_t idx = rowm * C3 + (size_t)h * CK + col;
            sp[s][col] = __half2float(qkv[idx + 1024]) * keep;
            sv[s][col] = __half2float(qkv[idx + 2048]) * keep;
        }
        __syncthreads();
        #pragma unroll
        for (int s = 0; s < 8; s++) {
            float4 a  = *reinterpret_cast<const float4*>(&sp[s][r0]);
            float4 bb = *reinterpret_cast<const float4*>(&sv[s][c0]);
            float ar[4] = {a.x, a.y, a.z, a.w};
            float br[4] = {bb.x, bb.y, bb.z, bb.w};
            #pragma unroll
            for (int i = 0; i < 4; i++)
                #pragma unroll
                for (int j = 0; j < 4; j++)
                    acc[i][j] += ar[i] * br[j];
        }
        if (tid < CK) {
            #pragma unroll
            for (int s = 0; s < 8; s++) ks += sp[s][tid];
        }
        __syncthreads();
    }

    float* kvp = g_kv + (size_t)bh * CK * CK;
    #pragma unroll
    for (int i = 0; i < 4; i++)
        #pragma unroll
        for (int j = 0; j < 4; j++)
            atomicAdd(&kvp[(r0 + i) * CK + c0 + j], acc[i][j]);
    if (tid < CK) atomicAdd(&g_ksum[bh * CK + tid], ks);
}

// ---------------------------------------------------------------------------
// attn: reads phi_q from fused qkv (stride C3), writes gh_attn (stride CD)
// ---------------------------------------------------------------------------
__global__ void attn_kernel(const __half* __restrict__ qkv,
                            __half* __restrict__ attn)
{
    __shared__ float skv[CK][CK];
    __shared__ float sks[CK];
    __shared__ float sq[8][CK];

    int bh = blockIdx.x, tb = blockIdx.y;
    int b = bh / CH, h = bh % CH;
    int tid = threadIdx.x;

    const float* kvp = g_kv + (size_t)bh * CK * CK;
    for (int i = tid; i < CK * CK; i += 256) skv[i >> 6][i & 63] = kvp[i];
    if (tid < CK) sks[tid] = g_ksum[bh * CK + tid];
    __syncthreads();

    int w = tid >> 5, l = tid & 31;
    for (int it = 0; it < 16; it++) {
        int t = tb * 128 + w * 16 + it;
        size_t rowq = ((size_t)b * CT + t) * C3 + (size_t)h * CK;
        size_t rowa = ((size_t)b * CT + t) * CD + (size_t)h * CK;
        sq[w][l]      = __half2float(qkv[rowq + l]);
        sq[w][l + 32] = __half2float(qkv[rowq + l + 32]);
        __syncwarp();
        float n0 = 0.f, n1 = 0.f, den = DEN_EPS;
        #pragma unroll
        for (int k = 0; k < CK; k++) {
            float qv = sq[w][k];
            n0  += qv * skv[k][l];
            n1  += qv * skv[k][l + 32];
            den += qv * sks[k];
        }
        float inv = 1.f / den;
        attn[rowa + l]      = __float2half_rn(n0 * inv);
        attn[rowa + l + 32] = __float2half_rn(n1 * inv);
        __syncwarp();
    }
}

// ---------------------------------------------------------------------------
// Host launcher
// ---------------------------------------------------------------------------
extern "C" void kernel_launch(void* const* d_in, const int* in_sizes, int n_in,
                              void* d_out, int out_size)
{
    const float* x    = (const float*)d_in[0];
    const unsigned char* mask = (const unsigned char*)d_in[1];
    const float* Wq   = (const float*)d_in[2];
    const float* bq   = (const float*)d_in[3];
    const float* Wk   = (const float*)d_in[4];
    const float* bk   = (const float*)d_in[5];
    const float* Wv   = (const float*)d_in[6];
    const float* bv   = (const float*)d_in[7];
    const float* Wo   = (const float*)d_in[8];
    const float* bo   = (const float*)d_in[9];
    const float* ln1w = (const float*)d_in[10];
    const float* ln1b = (const float*)d_in[11];
    const float* ln2w = (const float*)d_in[12];
    const float* ln2b = (const float*)d_in[13];
    const float* W1   = (const float*)d_in[14];
    const float* b1   = (const float*)d_in[15];
    const float* W2   = (const float*)d_in[16];
    const float* b2   = (const float*)d_in[17];
    float* out = (float*)d_out;

    void *pxn, *pqkv, *pattn, *py, *ph, *pwh, *px2, *pkv, *pks, *pbq;
    cudaGetSymbolAddress(&pxn, gh_xn);
    cudaGetSymbolAddress(&pqkv, gh_qkv);
    cudaGetSymbolAddress(&pattn, gh_attn);
    cudaGetSymbolAddress(&py, gh_y);
    cudaGetSymbolAddress(&ph, gh_h);
    cudaGetSymbolAddress(&pwh, gh_w);
    cudaGetSymbolAddress(&px2, g_x2);
    cudaGetSymbolAddress(&pkv, g_kv);
    cudaGetSymbolAddress(&pks, g_ksum);
    cudaGetSymbolAddress(&pbq, g_bqkv);

    __half* xn  = (__half*)pxn;
    __half* qkv = (__half*)pqkv;
    __half* atb = (__half*)pattn;
    __half* yb  = (__half*)py;
    __half* hb  = (__half*)ph;
    __half* wh  = (__half*)pwh;
    float*  x2  = (float*)px2;
    float*  kvb = (float*)pkv;
    float*  ksb = (float*)pks;
    float*  bqkv= (float*)pbq;

    cudaFuncSetAttribute(gemm_h_kernel, cudaFuncAttributeMaxDynamicSharedMemorySize, GEMM_SMEM);

    // 0. Convert + pack weights, concat QKV bias
    wconv_all_kernel<<<12288, 256>>>(Wq, Wk, Wv, Wo, W1, W2, bq, bk, bv, wh);

    // 1. LN1 -> fp16
    ln_kernel<<<CN, 256>>>(x, ln1w, ln1b, xn);

    // 2. Fused QKV projection (phi on Q,K cols) -> gh_qkv [CN, 3072]
    dim3 g3(C3 / GBN, CN / GBM);         // (24, 128)
    gemm_h_kernel<<<g3, 256, GEMM_SMEM>>>(xn, wh, bqkv, nullptr, qkv, C3, CD, 4);

    // 3. zero kv/ksum accumulators
    zero_kernel<<<(CB*CH*CK*CK + 255) / 256, 256>>>(kvb, CB*CH*CK*CK);
    zero_kernel<<<(CB*CH*CK + 255) / 256, 256>>>(ksb, CB*CH*CK);

    // 4. kv + ksum reduction (masked)
    kv_kernel<<<dim3(CB*CH, 8), 256>>>(qkv, mask);

    // 5. numerator / denominator -> fp16
    attn_kernel<<<dim3(CB*CH, CT / 128), 256>>>(qkv, atb);

    // 6. O projection + residual -> fp32 x2
    dim3 gD(CD / GBN, CN / GBM);
    gemm_h_kernel<<<gD, 256, GEMM_SMEM>>>(atb, wh + WT_O, bo, x, x2, CD, CD, 3);

    // 7. LN2 -> fp16
    ln_kernel<<<CN, 256>>>(x2, ln2w, ln2b, yb);

    // 8. FFN1 + exact GELU -> fp16
    dim3 gF(CF / GBN, CN / GBM);
    gemm_h_kernel<<<gF, 256, GEMM_SMEM>>>(yb, wh + WT_1, b1, nullptr, hb, CF, CD, 2);

    // 9. FFN2 + residual -> fp32 output
    gemm_h_kernel<<<gD, 256, GEMM_SMEM>>>(hb, wh + WT_2, b2, x2, out, CD, CF, 3);
}